// round 1
// baseline (speedup 1.0000x reference)
#include <cuda_runtime.h>
#include <cstdint>

namespace {

constexpr int BATCH     = 20000;
constexpr int MTOT      = 49;
constexpr int KDIM      = 128;   // IN
constexpr int NDIM      = 128;   // OUT
constexpr int TILE_ROWS = 128;
constexpr int KCHUNK    = 32;
constexpr int SPAD      = 36;                      // padded K stride (floats); 36 % 32 == 4 -> conflict-free frags
constexpr int BUF_FLOATS = TILE_ROWS * SPAD;       // 4608 floats per buffer
constexpr int NTHREADS  = 256;
constexpr int SMEM_BYTES = 4 * BUF_FLOATS * (int)sizeof(float);  // A0,A1,W0,W1 = 73728 B

__device__ __forceinline__ uint32_t cvt_tf32(float x) {
    uint32_t r;
    asm("cvt.rna.tf32.f32 %0, %1;" : "=r"(r) : "f"(x));
    return r;
}

__device__ __forceinline__ void mma_tf32(float* c, const uint32_t* a, uint32_t b0, uint32_t b1) {
    asm volatile(
        "mma.sync.aligned.m16n8k8.row.col.f32.tf32.tf32.f32 "
        "{%0,%1,%2,%3}, {%4,%5,%6,%7}, {%8,%9}, {%0,%1,%2,%3};"
        : "+f"(c[0]), "+f"(c[1]), "+f"(c[2]), "+f"(c[3])
        : "r"(a[0]), "r"(a[1]), "r"(a[2]), "r"(a[3]), "r"(b0), "r"(b1));
}

__device__ __forceinline__ void cp_async16(uint32_t dst, const void* src, int srcsize) {
    asm volatile("cp.async.cg.shared.global [%0], [%1], 16, %2;"
                 :: "r"(dst), "l"(src), "r"(srcsize));
}

__global__ void __launch_bounds__(NTHREADS, 2)
so3_linear_kernel(const float* __restrict__ in,
                  const float* __restrict__ w,
                  const float* __restrict__ bias,
                  float* __restrict__ out)
{
    extern __shared__ float smem[];
    // layout: A[2][128][36] then W[2][128][36]

    const int m       = blockIdx.y;
    const int rowBase = blockIdx.x * TILE_ROWS;

    int l = 0;
    while ((l + 1) * (l + 1) <= m) l++;
    const float* wl = w + (size_t)l * NDIM * KDIM;

    const int tid  = threadIdx.x;
    const int lane = tid & 31;
    const int wid  = tid >> 5;
    const int g    = lane >> 2;   // groupID (0..7)
    const int t    = lane & 3;    // thread-in-group (0..3)
    const int warp_row = (wid & 3) * 32;   // 0,32,64,96
    const int warp_col = (wid >> 2) * 64;  // 0,64

    const uint32_t sbase = (uint32_t)__cvta_generic_to_shared(smem);

    auto load_chunk = [&](int kc, int buf) {
        // A tile: 128 rows x 32 k (1024 float4)
        #pragma unroll
        for (int i = 0; i < 4; i++) {
            int idx = tid + i * NTHREADS;
            int row = idx >> 3, q = idx & 7;
            int b   = rowBase + row;
            int bc  = (b < BATCH) ? b : (BATCH - 1);
            const float* src = in + (((size_t)bc * MTOT + m) * KDIM + kc + q * 4);
            uint32_t dst = sbase + (uint32_t)((buf * BUF_FLOATS + row * SPAD + q * 4) * 4);
            cp_async16(dst, src, (b < BATCH) ? 16 : 0);
        }
        // W tile: 128 n x 32 k (always in bounds)
        #pragma unroll
        for (int i = 0; i < 4; i++) {
            int idx = tid + i * NTHREADS;
            int n = idx >> 3, q = idx & 7;
            const float* src = wl + ((size_t)n * KDIM + kc + q * 4);
            uint32_t dst = sbase + (uint32_t)(((2 + buf) * BUF_FLOATS + n * SPAD + q * 4) * 4);
            cp_async16(dst, src, 16);
        }
        asm volatile("cp.async.commit_group;");
    };

    float acc[2][8][4] = {};
    uint32_t a_frag[2][4];

    load_chunk(0, 0);

    #pragma unroll
    for (int kc = 0; kc < KDIM / KCHUNK; kc++) {
        if (kc < 3) {
            load_chunk((kc + 1) * KCHUNK, (kc + 1) & 1);
            asm volatile("cp.async.wait_group 1;");
        } else {
            asm volatile("cp.async.wait_group 0;");
        }
        __syncthreads();

        const float* A = smem + (kc & 1) * BUF_FLOATS;
        const float* W = smem + (2 + (kc & 1)) * BUF_FLOATS;

        #pragma unroll
        for (int ks = 0; ks < 4; ks++) {
            const int k0 = ks * 8;
            #pragma unroll
            for (int mi = 0; mi < 2; mi++) {
                int r = warp_row + mi * 16 + g;
                a_frag[mi][0] = cvt_tf32(A[r * SPAD + k0 + t]);
                a_frag[mi][1] = cvt_tf32(A[(r + 8) * SPAD + k0 + t]);
                a_frag[mi][2] = cvt_tf32(A[r * SPAD + k0 + t + 4]);
                a_frag[mi][3] = cvt_tf32(A[(r + 8) * SPAD + k0 + t + 4]);
            }
            #pragma unroll
            for (int ni = 0; ni < 8; ni++) {
                int c = warp_col + ni * 8 + g;
                uint32_t b0 = cvt_tf32(W[c * SPAD + k0 + t]);
                uint32_t b1 = cvt_tf32(W[c * SPAD + k0 + t + 4]);
                mma_tf32(acc[0][ni], a_frag[0], b0, b1);
                mma_tf32(acc[1][ni], a_frag[1], b0, b1);
            }
        }
        __syncthreads();
    }

    // Epilogue: store + bias on m==0
    const bool addb = (m == 0);
    #pragma unroll
    for (int mi = 0; mi < 2; mi++) {
        #pragma unroll
        for (int ni = 0; ni < 8; ni++) {
            int c  = warp_col + ni * 8 + 2 * t;
            int r0 = rowBase + warp_row + mi * 16 + g;
            float2 v0 = make_float2(acc[mi][ni][0], acc[mi][ni][1]);
            float2 v1 = make_float2(acc[mi][ni][2], acc[mi][ni][3]);
            if (addb) {
                float b0v = bias[c], b1v = bias[c + 1];
                v0.x += b0v; v0.y += b1v;
                v1.x += b0v; v1.y += b1v;
            }
            if (r0 < BATCH)
                *reinterpret_cast<float2*>(out + (((size_t)r0 * MTOT + m) * NDIM + c)) = v0;
            if (r0 + 8 < BATCH)
                *reinterpret_cast<float2*>(out + (((size_t)(r0 + 8) * MTOT + m) * NDIM + c)) = v1;
        }
    }
}

}  // namespace

extern "C" void kernel_launch(void* const* d_in, const int* in_sizes, int n_in,
                              void* d_out, int out_size) {
    (void)in_sizes; (void)n_in; (void)out_size;
    const float* in   = (const float*)d_in[0];
    const float* w    = (const float*)d_in[1];
    const float* bias = (const float*)d_in[2];
    float* out        = (float*)d_out;

    cudaFuncSetAttribute(so3_linear_kernel,
                         cudaFuncAttributeMaxDynamicSharedMemorySize, SMEM_BYTES);

    dim3 grid((BATCH + TILE_ROWS - 1) / TILE_ROWS, MTOT);
    so3_linear_kernel<<<grid, NTHREADS, SMEM_BYTES>>>(in, w, bias, out);
}